// round 13
// baseline (speedup 1.0000x reference)
#include <cuda_runtime.h>
#include <cuda_bf16.h>
#include <cstdint>
using bf16 = __nv_bfloat16;

#define Bx   4
#define Tx   2048
#define Dx   1024
#define Hx   16
#define HDx  64
#define NFx  128
#define BTx  (Bx*Tx)
#define BHx  (Bx*Hx)
#define CHx  64
#define NCx  (Tx/CHx)       // 32
#define SCANx (BHx*NCx)     // 2048
#define INV_SQRT_NF 0.08838834764831845f

// ---------------- static scratch ----------------
__device__ bf16  g_XH[BTx*Dx],  g_XL[BTx*Dx];
__device__ bf16  g_WH[3*Dx*Dx], g_WL[3*Dx*Dx];     // [n][k]
__device__ bf16  g_WOH[Dx*Dx],  g_WOL[Dx*Dx];      // [n][k]
__device__ bf16  g_WFH[NFx*HDx], g_WFL[NFx*HDx];   // [f][d] split
__device__ float g_Q[BHx*Tx*HDx], g_K[BHx*Tx*HDx];
__device__ bf16  g_VH[BHx*Tx*HDx], g_VL[BHx*Tx*HDx];
__device__ bf16  g_QPH[BHx*Tx*NFx], g_QPL[BHx*Tx*NFx];
__device__ bf16  g_KPH[BHx*Tx*NFx], g_KPL[BHx*Tx*NFx];
__device__ float g_SC[SCANx*NFx*HDx], g_ZC[SCANx*NFx];
__device__ float g_SP[SCANx*NFx*HDx], g_ZP[SCANx*NFx];
__device__ bf16  g_YH[BTx*Dx], g_YL[BTx*Dx];

__device__ __forceinline__ void split_bf(float v, bf16 &h, bf16 &l) {
    h = __float2bfloat16(v);
    l = __float2bfloat16(v - __bfloat162float(h));
}
__device__ __forceinline__ float f2(bf16 v) { return __bfloat162float(v); }
__device__ __forceinline__ unsigned ldu(const bf16* p) {
    return *reinterpret_cast<const unsigned*>(p);
}
__device__ __forceinline__ void mma16816(float c[4], const unsigned a[4], const unsigned b[2]) {
    asm volatile(
        "mma.sync.aligned.m16n8k16.row.col.f32.bf16.bf16.f32 "
        "{%0,%1,%2,%3},{%4,%5,%6,%7},{%8,%9},{%0,%1,%2,%3};\n"
        : "+f"(c[0]), "+f"(c[1]), "+f"(c[2]), "+f"(c[3])
        : "r"(a[0]), "r"(a[1]), "r"(a[2]), "r"(a[3]), "r"(b[0]), "r"(b[1]));
}
__device__ __forceinline__ uint32_t s2u(const void* p) {
    uint32_t a;
    asm("{ .reg .u64 t; cvta.to.shared.u64 t, %1; cvt.u32.u64 %0, t; }" : "=r"(a) : "l"(p));
    return a;
}
__device__ __forceinline__ void cpa16s(uint32_t dst, const void* src) {
    asm volatile("cp.async.cg.shared.global [%0],[%1],16;\n" :: "r"(dst), "l"(src));
}
#define CPCOMMIT asm volatile("cp.async.commit_group;\n")
__device__ __forceinline__ void ldsm4(unsigned r[4], uint32_t a) {
    asm volatile("ldmatrix.sync.aligned.m8n8.x4.shared.b16 {%0,%1,%2,%3}, [%4];"
        : "=r"(r[0]), "=r"(r[1]), "=r"(r[2]), "=r"(r[3]) : "r"(a));
}

// ---------------- prep ----------------
__global__ void k_split_x(const float* __restrict__ x) {
    int i = blockIdx.x*256 + threadIdx.x;
    if (i < BTx*Dx) split_bf(x[i], g_XH[i], g_XL[i]);
}
// all weight prep in ONE launch: z<3 -> Wq/Wk/Wv, z==3 -> Wo, z==4 -> Wf
__global__ void k_prepw(const float* __restrict__ Wq, const float* __restrict__ Wk,
                        const float* __restrict__ Wv, const float* __restrict__ Wo,
                        const float* __restrict__ Wf) {
    if (blockIdx.z == 4) {
        if (blockIdx.y != 0) return;
        int i = blockIdx.x*256 + threadIdx.y*32 + threadIdx.x;
        if (i < NFx*HDx)
            split_bf(Wf[(i & 63)*NFx + (i >> 6)], g_WFH[i], g_WFL[i]);
        return;
    }
    __shared__ float tile[32][33];
    const float* W = blockIdx.z == 0 ? Wq : (blockIdx.z == 1 ? Wk : (blockIdx.z == 2 ? Wv : Wo));
    bf16* Dh = blockIdx.z == 3 ? g_WOH : g_WH + blockIdx.z*Dx*Dx;
    bf16* Dl = blockIdx.z == 3 ? g_WOL : g_WL + blockIdx.z*Dx*Dx;
    int x = blockIdx.x*32 + threadIdx.x;
    int y0 = blockIdx.y*32;
    #pragma unroll
    for (int j = 0; j < 32; j += 8)
        tile[threadIdx.y+j][threadIdx.x] = W[(y0+threadIdx.y+j)*1024 + x];
    __syncthreads();
    int n = blockIdx.x*32 + threadIdx.y;
    #pragma unroll
    for (int j = 0; j < 32; j += 8) {
        float v = tile[threadIdx.x][threadIdx.y+j];
        split_bf(v, Dh[(n+j)*1024 + y0 + threadIdx.x], Dl[(n+j)*1024 + y0 + threadIdx.x]);
    }
}

// ---------------- mma.sync split-3 GEMM, 128Mx128N tile, 2 CTAs/SM, 3-stage ----------------
#define SUBB 8192
#define STGB (4*SUBB)
#define GSMEM (3*STGB)
__global__ __launch_bounds__(256,2) void k_gemm(
        const bf16* __restrict__ Ah_, const bf16* __restrict__ Al_,
        const bf16* __restrict__ Bh_, const bf16* __restrict__ Bl_,
        int mode, float* __restrict__ out) {
    extern __shared__ char gsm[];
    uint32_t sb = s2u(gsm);
    int tid = threadIdx.x, lane = tid & 31, warp = tid >> 5;
    int g = lane >> 2, tg = lane & 3;
    int wm = warp >> 1, wn = warp & 1;            // 4x2 warps, each 32Mx64N
    int m0 = blockIdx.y*128, n0 = blockIdx.x*128;
    float acc[2][8][4] = {};

    auto load_stage = [&](int s, int kt) {
        uint32_t st = sb + s*STGB;
        #pragma unroll
        for (int i = 0; i < 8; i++) {
            int idx = tid + i*256;
            int arr = idx >> 9, c = idx & 511;
            int row = c >> 2, seg = c & 3;
            const bf16* gp = (arr == 0 ? Ah_ : arr == 1 ? Al_ : arr == 2 ? Bh_ : Bl_)
                           + (size_t)((arr < 2 ? m0 : n0) + row)*1024 + kt*32 + seg*8;
            uint32_t o = row*64 + ((seg ^ ((row>>1)&3))*16);
            cpa16s(st + arr*SUBB + o, gp);
        }
        CPCOMMIT;
    };
    load_stage(0, 0);
    load_stage(1, 1);
    for (int kt = 0; kt < 32; kt++) {
        if (kt == 31) asm volatile("cp.async.wait_group 0;\n");
        else          asm volatile("cp.async.wait_group 1;\n");
        __syncthreads();
        if (kt + 2 < 32) load_stage((kt+2)%3, kt+2);
        uint32_t st = sb + (kt%3)*STGB;
        #pragma unroll
        for (int kc = 0; kc < 2; kc++) {
            int sega = kc*2 + (lane >> 4);
            unsigned aH[2][4], aL[2][4], bH[4][4], bL[4][4];
            #pragma unroll
            for (int im = 0; im < 2; im++) {
                int r = wm*32 + im*16 + (lane & 15);
                uint32_t off = r*64 + ((sega ^ ((r>>1)&3))*16);
                ldsm4(aH[im], st + off);
                ldsm4(aL[im], st + SUBB + off);
            }
            #pragma unroll
            for (int p = 0; p < 4; p++) {
                int r = wn*64 + p*16 + (lane & 15);
                uint32_t off = r*64 + ((sega ^ ((r>>1)&3))*16);
                ldsm4(bH[p], st + 2*SUBB + off);
                ldsm4(bL[p], st + 3*SUBB + off);
            }
            #pragma unroll
            for (int im = 0; im < 2; im++)
                #pragma unroll
                for (int p = 0; p < 4; p++) {
                    unsigned b0h[2] = {bH[p][0], bH[p][2]}, b1h[2] = {bH[p][1], bH[p][3]};
                    unsigned b0l[2] = {bL[p][0], bL[p][2]}, b1l[2] = {bL[p][1], bL[p][3]};
                    mma16816(acc[im][2*p],   aH[im], b0h);
                    mma16816(acc[im][2*p],   aH[im], b0l);
                    mma16816(acc[im][2*p],   aL[im], b0h);
                    mma16816(acc[im][2*p+1], aH[im], b1h);
                    mma16816(acc[im][2*p+1], aH[im], b1l);
                    mma16816(acc[im][2*p+1], aL[im], b1h);
                }
        }
    }
    #pragma unroll
    for (int im = 0; im < 2; im++)
        #pragma unroll
        for (int in = 0; in < 8; in++)
            #pragma unroll
            for (int e = 0; e < 4; e++) {
                int row = m0 + wm*32 + im*16 + g + ((e>>1)<<3);
                int col = n0 + wn*64 + in*8 + tg*2 + (e&1);
                float v = acc[im][in][e];
                if (mode == 0) {
                    int b = row >> 11, t = row & 2047;
                    int which = col >> 10, cc = col & 1023;
                    int off = ((b*Hx + (cc >> 6))*Tx + t)*HDx + (cc & 63);
                    if (which == 0)      g_Q[off] = v;
                    else if (which == 1) g_K[off] = v;
                    else                 split_bf(v, g_VH[off], g_VL[off]);
                } else {
                    out[(size_t)row*1024 + col] = v;
                }
            }
}

// ---------------- feature map via split-3 MMA: 128 tokens x 128 feats x K64 ----------------
#define FP 72
#define FEAT_SMEM (128*65*4 + 4*128*FP*2 + 128*4)
__global__ __launch_bounds__(256,2) void k_feat() {
    extern __shared__ char fsm[];
    float* sfq = (float*)fsm;                    // [t][65] fp32 staging
    bf16* sqh = (bf16*)(sfq + 128*65);
    bf16* sql = sqh + 128*FP;
    bf16* swh = sql + 128*FP;
    bf16* swl = swh + 128*FP;
    float* sqn = (float*)(swl + 128*FP);
    int tid = threadIdx.x, lane = tid & 31, warp = tid >> 5;
    int g = lane >> 2, tg = lane & 3;
    const float* src = blockIdx.y ? g_K : g_Q;
    bf16* dh = blockIdx.y ? g_KPH : g_QPH;
    bf16* dl = blockIdx.y ? g_KPL : g_QPL;
    int tokbase = blockIdx.x * 128;

    #pragma unroll
    for (int i = 0; i < 32; i++) {
        int idx = tid + i*256;                   // 8192
        int t = idx >> 6, d = idx & 63;
        sfq[t*65 + d] = src[(tokbase + t)*HDx + d];
        swh[t*FP + d] = g_WFH[idx];              // t==f here
        swl[t*FP + d] = g_WFL[idx];
    }
    __syncthreads();
    if (tid < 128) {
        float s = 0.f;
        #pragma unroll 16
        for (int d = 0; d < 64; d++) { float q = sfq[tid*65+d]; s += q*q; }
        sqn[tid] = 0.5f*s;
    }
    #pragma unroll
    for (int i = 0; i < 32; i++) {
        int idx = tid + i*256;
        int t = idx >> 6, d = idx & 63;
        split_bf(sfq[t*65+d], sqh[t*FP+d], sql[t*FP+d]);
    }
    __syncthreads();

    int r0 = warp*16;
    float acc[16][4] = {};
    #pragma unroll
    for (int ks = 0; ks < 4; ks++) {
        int kc = ks*16;
        unsigned aH[4], aL[4];
        aH[0] = ldu(&sqh[(r0+g)*FP+kc+2*tg]);   aH[1] = ldu(&sqh[(r0+g+8)*FP+kc+2*tg]);
        aH[2] = ldu(&sqh[(r0+g)*FP+kc+2*tg+8]); aH[3] = ldu(&sqh[(r0+g+8)*FP+kc+2*tg+8]);
        aL[0] = ldu(&sql[(r0+g)*FP+kc+2*tg]);   aL[1] = ldu(&sql[(r0+g+8)*FP+kc+2*tg]);
        aL[2] = ldu(&sql[(r0+g)*FP+kc+2*tg+8]); aL[3] = ldu(&sql[(r0+g+8)*FP+kc+2*tg+8]);
        #pragma unroll
        for (int jn = 0; jn < 16; jn++) {
            int r = jn*8 + g;
            unsigned bH[2], bL[2];
            bH[0] = ldu(&swh[r*FP+kc+2*tg]); bH[1] = ldu(&swh[r*FP+kc+2*tg+8]);
            bL[0] = ldu(&swl[r*FP+kc+2*tg]); bL[1] = ldu(&swl[r*FP+kc+2*tg+8]);
            mma16816(acc[jn], aH, bH);
            mma16816(acc[jn], aH, bL);
            mma16816(acc[jn], aL, bH);
        }
    }
    #pragma unroll
    for (int jn = 0; jn < 16; jn++)
        #pragma unroll
        for (int e = 0; e < 4; e++) {
            int row = r0 + g + ((e>>1)<<3);
            int f = jn*8 + 2*tg + (e&1);
            float p = __expf(acc[jn][e] - sqn[row]) * INV_SQRT_NF;
            int o = (tokbase + row)*NFx + f;
            split_bf(p, dh[o], dl[o]);
        }
}

// ---------------- pass A: S_c = kp^T v (fp32, conflict-free), chunk=64 ----------------
#define PASSA_SMEM ((64*129 + 64*65)*4)
__global__ __launch_bounds__(256) void k_passA() {
    extern __shared__ float asm_[];
    float* skp = asm_;              // [t*129+f]
    float* svT = skp + 64*129;      // [d*65+t]
    int cta = blockIdx.x, tid = threadIdx.x;
    int base = (cta >> 5)*Tx + (cta & 31)*CHx;
    #pragma unroll
    for (int i = 0; i < 32; i++) {
        int idx = tid + i*256;
        int t = idx >> 7, f = idx & 127;
        skp[t*129+f] = f2(g_KPH[(base+t)*NFx+f]) + f2(g_KPL[(base+t)*NFx+f]);
    }
    #pragma unroll
    for (int i = 0; i < 16; i++) {
        int idx = tid + i*256;
        int s = idx >> 6, d = idx & 63;
        svT[d*65+s] = f2(g_VH[(base+s)*HDx+d]) + f2(g_VL[(base+s)*HDx+d]);
    }
    __syncthreads();
    if (tid < 128) {
        float s = 0.f;
        #pragma unroll 16
        for (int t = 0; t < 64; t++) s += skp[t*129 + tid];
        g_ZC[cta*NFx + tid] = s;
    }
    int f0 = (tid >> 3)*4, d0 = (tid & 7)*8;
    float acc[4][8] = {};
    #pragma unroll 4
    for (int t = 0; t < 64; t++) {
        float kv[4], vv[8];
        #pragma unroll
        for (int i = 0; i < 4; i++) kv[i] = skp[t*129 + f0 + i];
        #pragma unroll
        for (int j = 0; j < 8; j++) vv[j] = svT[(d0+j)*65 + t];
        #pragma unroll
        for (int i = 0; i < 4; i++)
            #pragma unroll
            for (int j = 0; j < 8; j++) acc[i][j] += kv[i]*vv[j];
    }
    #pragma unroll
    for (int i = 0; i < 4; i++)
        #pragma unroll
        for (int j = 0; j < 8; j++)
            g_SC[cta*(NFx*HDx) + (f0+i)*HDx + d0 + j] = acc[i][j];
}

// ---------------- exclusive prefix over chunks, software-prefetched ----------------
__global__ __launch_bounds__(256) void k_prefix() {
    int bh = blockIdx.x, fg = blockIdx.y, tid = threadIdx.x;
    int cb = bh*NCx;
    int b0 = cb*(NFx*HDx) + fg*512;
    float s0 = 0.f, s1 = 0.f, z = 0.f;
    float a0 = g_SC[b0 + tid], a1 = g_SC[b0 + 256 + tid];
    float zc = (tid < 8) ? g_ZC[cb*NFx + fg*8 + tid] : 0.f;
    #pragma unroll 4
    for (int c = 0; c < NCx; c++) {
        float n0 = 0.f, n1 = 0.f, nz = 0.f;
        if (c + 1 < NCx) {
            int bn = b0 + NFx*HDx;
            n0 = g_SC[bn + tid]; n1 = g_SC[bn + 256 + tid];
            if (tid < 8) nz = g_ZC[(cb+c+1)*NFx + fg*8 + tid];
        }
        g_SP[b0 + tid] = s0;        s0 += a0;
        g_SP[b0 + 256 + tid] = s1;  s1 += a1;
        if (tid < 8) { g_ZP[(cb+c)*NFx + fg*8 + tid] = z; z += zc; }
        a0 = n0; a1 = n1; zc = nz; b0 += NFx*HDx;
    }
}

// ---------------- pass C: MMA intra + inter, chunk=64, 2 CTAs/SM ----------------
#define CP1 132
#define CP2 72
#define PASSC_SMEM ((4*64*CP1 + 4*64*CP2)*2 + (NFx+64)*4)
__global__ __launch_bounds__(256,2) void k_passC() {
    extern __shared__ char csm[];
    bf16* sqh = (bf16*)csm;            bf16* sql = sqh + 64*CP1;
    bf16* skh = sql + 64*CP1;          bf16* skl = skh + 64*CP1;
    bf16* sAh = skl + 64*CP1;          bf16* sAl = sAh + 64*CP2;
    bf16* svh = sAl + 64*CP2;          bf16* svl = svh + 64*CP2;
    bf16* sph = skh;                   bf16* spl = skl;   // alias: kp dead after phase1
    float* szp  = (float*)(svl + 64*CP2);
    float* sden = szp + NFx;

    int cta = blockIdx.x, tid = threadIdx.x;
    int bh = cta >> 5, c = cta & 31;
    int base = bh*Tx + c*CHx;
    int lane = tid & 31, warp = tid >> 5, g = lane >> 2, tg = lane & 3;

    #pragma unroll
    for (int i = 0; i < 32; i++) {
        int idx = tid + i*256;
        int t = idx >> 7, f = idx & 127;
        sqh[t*CP1+f] = g_QPH[(base+t)*NFx+f];  sql[t*CP1+f] = g_QPL[(base+t)*NFx+f];
        skh[t*CP1+f] = g_KPH[(base+t)*NFx+f];  skl[t*CP1+f] = g_KPL[(base+t)*NFx+f];
    }
    if (tid < NFx) szp[tid] = g_ZP[cta*NFx + tid];
    __syncthreads();

    // phase 1: A[t][s] = qp.kp^T (M64 N64 K128)
    {
        int wm = warp & 1, wn = warp >> 1;
        float acc[2][2][4] = {};
        #pragma unroll
        for (int ks = 0; ks < 8; ks++) {
            int kc = ks*16;
            unsigned aH[2][4], aL[2][4], bH[2][2], bL[2][2];
            #pragma unroll
            for (int im = 0; im < 2; im++) {
                int r = wm*32 + im*16;
                aH[im][0] = ldu(&sqh[(r+g)*CP1+kc+2*tg]);   aH[im][1] = ldu(&sqh[(r+g+8)*CP1+kc+2*tg]);
                aH[im][2] = ldu(&sqh[(r+g)*CP1+kc+2*tg+8]); aH[im][3] = ldu(&sqh[(r+g+8)*CP1+kc+2*tg+8]);
                aL[im][0] = ldu(&sql[(r+g)*CP1+kc+2*tg]);   aL[im][1] = ldu(&sql[(r+g+8)*CP1+kc+2*tg]);
                aL[im][2] = ldu(&sql[(r+g)*CP1+kc+2*tg+8]); aL[im][3] = ldu(&sql[(r+g+8)*CP1+kc+2*tg+8]);
            }
            #pragma unroll
            for (int in = 0; in < 2; in++) {
                int r = wn*16 + in*8 + g;
                bH[in][0] = ldu(&skh[r*CP1+kc+2*tg]); bH[in][1] = ldu(&skh[r*CP1+kc+2*tg+8]);
                bL[in][0] = ldu(&skl[r*CP1+kc+2*tg]); bL[in][1] = ldu(&skl[r*CP1+kc+2*tg+8]);
            }
            #pragma unroll
            for (int im = 0; im < 2; im++)
                #pragma unroll
                for (int in = 0; in < 2; in++) {
                    mma16816(acc[im][in], aH[im], bH[in]);
                    mma16816(acc[im][in], aH[im], bL[in]);
                    mma16816(acc[im][in], aL[im], bH[in]);
                }
        }
        #pragma unroll
        for (int im = 0; im < 2; im++)
            #pragma unroll
            for (int in = 0; in < 2; in++)
                #pragma unroll
                for (int e = 0; e < 4; e++) {
                    int t = wm*32 + im*16 + g + ((e>>1)<<3);
                    int s = wn*16 + in*8 + 2*tg + (e&1);
                    float v = (s <= t) ? acc[im][in][e] : 0.f;
                    split_bf(v, sAh[t*CP2+s], sAl[t*CP2+s]);
                }
    }
    __syncthreads();   // all kp reads + A writes done before sk region reused for SP

    // load vT; SP into the freed kp region; den = rowsum(A) + qp.zp + eps
    #pragma unroll
    for (int i = 0; i < 16; i++) {
        int idx = tid + i*256;
        int s = idx >> 6, d = idx & 63;
        svh[d*CP2+s] = g_VH[(base+s)*HDx+d];  svl[d*CP2+s] = g_VL[(base+s)*HDx+d];
    }
    #pragma unroll
    for (int i = 0; i < 32; i++) {
        int idx = tid + i*256;
        int f = idx >> 6, d = idx & 63;
        float sp = g_SP[cta*(NFx*HDx) + f*HDx + d];
        split_bf(sp, sph[d*CP1+f], spl[d*CP1+f]);
    }
    if (tid < 64) {
        float rs = 0.f, qz = 0.f;
        #pragma unroll 8
        for (int s = 0; s < 64; s++) rs += f2(sAh[tid*CP2+s]) + f2(sAl[tid*CP2+s]);
        #pragma unroll 8
        for (int f = 0; f < NFx; f++) qz += (f2(sqh[tid*CP1+f]) + f2(sql[tid*CP1+f]))*szp[f];
        sden[tid] = rs + qz + 1e-6f;
    }
    __syncthreads();   // sv, sp, den visible

    // phase 2: y[t][d] = A.v + qp.SP (M64 N64, K=64 then K=128)
    int r0 = (warp & 3)*16, d0 = (warp >> 2)*32;
    float acc[4][4] = {};
    #pragma unroll
    for (int ks = 0; ks < 4; ks++) {
        int kc = ks*16;
        unsigned aH[4], aL[4];
        aH[0] = ldu(&sAh[(r0+g)*CP2+kc+2*tg]);   aH[1] = ldu(&sAh[(r0+g+8)*CP2+kc+2*tg]);
        aH[2] = ldu(&sAh[(r0+g)*CP2+kc+2*tg+8]); aH[3] = ldu(&sAh[(r0+g+8)*CP2+kc+2*tg+8]);
        aL[0] = ldu(&sAl[(r0+g)*CP2+kc+2*tg]);   aL[1] = ldu(&sAl[(r0+g+8)*CP2+kc+2*tg]);
        aL[2] = ldu(&sAl[(r0+g)*CP2+kc+2*tg+8]); aL[3] = ldu(&sAl[(r0+g+8)*CP2+kc+2*tg+8]);
        #pragma unroll
        for (int in = 0; in < 4; in++) {
            int r = d0 + in*8 + g;
            unsigned bH[2], bL[2];
            bH[0] = ldu(&svh[r*CP2+kc+2*tg]); bH[1] = ldu(&svh[r*CP2+kc+2*tg+8]);
            bL[0] = ldu(&svl[r*CP2+kc+2*tg]); bL[1] = ldu(&svl[r*CP2+kc+2*tg+8]);
            mma16816(acc[in], aH, bH);
            mma16816(acc[in], aH, bL);
            mma16816(acc[in], aL, bH);
        }
    }
    #pragma unroll
    for (int ks = 0; ks < 8; ks++) {
        int kc = ks*16;
        unsigned aH[4], aL[4];
        aH[0] = ldu(&sqh[(r0+g)*CP1+kc+2*tg]);   aH[1] = ldu(&sqh[(r0+g+8)*CP1+kc+2*tg]);
        aH[2] = ldu(&sqh[(r0+g)*CP1+kc+2*tg+8]); aH[3] = ldu(&sqh[(r0+g+8)*CP1+kc+2*tg+8]);
        aL[0] = ldu(&sql[(r0+g)*CP1+kc+2*tg]);   aL[1] = ldu(&sql[(r0+g+8)*CP1+kc+2*tg]);
        aL[2] = ldu(&sql[(r0+g)*CP1+kc+2*tg+8]); aL[3] = ldu(&sql[(r0+g+8)*CP1+kc+2*tg+8]);
        #pragma unroll
        for (int in = 0; in < 4; in++) {
            int r = d0 + in*8 + g;
            unsigned bH[2], bL[2];
            bH[0] = ldu(&sph[r*CP1+kc+2*tg]); bH[1] = ldu(&sph[r*CP1+kc+2*tg+8]);
            bL[0] = ldu(&spl[r*CP1+kc+2*tg]); bL[1] = ldu(&spl[r*CP1+kc+2*tg+8]);
            mma16816(acc[in], aH, bH);
            mma16816(acc[in], aH, bL);
            mma16816(acc[in], aL, bH);
        }
    }
    __syncthreads();
    int b = bh >> 4, h = bh & 15;
    #pragma unroll
    for (int in = 0; in < 4; in++)
        #pragma unroll
        for (int e = 0; e < 4; e++) {
            int t = r0 + g + ((e>>1)<<3);
            int d = d0 + in*8 + 2*tg + (e&1);
            float v = acc[in][e] / sden[t];
            int m = b*Tx + c*CHx + t;
            split_bf(v, g_YH[m*1024 + h*HDx + d], g_YL[m*1024 + h*HDx + d]);
        }
}

// ---------------- launch ----------------
extern "C" void kernel_launch(void* const* d_in, const int* in_sizes, int n_in,
                              void* d_out, int out_size) {
    const float* x  = (const float*)d_in[0];
    const float* Wq = (const float*)d_in[1];
    const float* Wk = (const float*)d_in[2];
    const float* Wv = (const float*)d_in[3];
    const float* Wo = (const float*)d_in[4];
    const float* Wf = (const float*)d_in[5];
    float* out = (float*)d_out;

    cudaFuncSetAttribute(k_gemm,  cudaFuncAttributeMaxDynamicSharedMemorySize, GSMEM);
    cudaFuncSetAttribute(k_feat,  cudaFuncAttributeMaxDynamicSharedMemorySize, FEAT_SMEM);
    cudaFuncSetAttribute(k_passA, cudaFuncAttributeMaxDynamicSharedMemorySize, PASSA_SMEM);
    cudaFuncSetAttribute(k_passC, cudaFuncAttributeMaxDynamicSharedMemorySize, PASSC_SMEM);

    bf16 *XH, *XL, *WH, *WL, *WOH, *WOL, *YH, *YL;
    cudaGetSymbolAddress((void**)&XH, g_XH);   cudaGetSymbolAddress((void**)&XL, g_XL);
    cudaGetSymbolAddress((void**)&WH, g_WH);   cudaGetSymbolAddress((void**)&WL, g_WL);
    cudaGetSymbolAddress((void**)&WOH, g_WOH); cudaGetSymbolAddress((void**)&WOL, g_WOL);
    cudaGetSymbolAddress((void**)&YH, g_YH);   cudaGetSymbolAddress((void**)&YL, g_YL);

    k_split_x<<<BTx*Dx/256, 256>>>(x);                                   // 1
    k_prepw<<<dim3(32,32,5), dim3(32,8)>>>(Wq, Wk, Wv, Wo, Wf);          // 2
    k_gemm<<<dim3(24, 64), 256, GSMEM>>>(XH, XL, WH, WL, 0, nullptr);    // 3
    k_feat<<<dim3(BHx*Tx/128, 2), 256, FEAT_SMEM>>>();                   // 4 <- profile target
    k_passA<<<SCANx, 256, PASSA_SMEM>>>();                               // 5
    k_prefix<<<dim3(BHx, 16), 256>>>();                                  // 6
    k_passC<<<SCANx, 256, PASSC_SMEM>>>();                               // 7
    k_gemm<<<dim3(8, 64), 256, GSMEM>>>(YH, YL, WOH, WOL, 1, out);       // 8
}

// round 16
// speedup vs baseline: 1.0960x; 1.0960x over previous
#include <cuda_runtime.h>
#include <cuda_bf16.h>
#include <cstdint>
using bf16 = __nv_bfloat16;

#define Bx   4
#define Tx   2048
#define Dx   1024
#define Hx   16
#define HDx  64
#define NFx  128
#define BTx  (Bx*Tx)
#define BHx  (Bx*Hx)
#define CHx  64
#define NCx  (Tx/CHx)       // 32
#define SCANx (BHx*NCx)     // 2048
#define INV_SQRT_NF 0.08838834764831845f

// ---------------- static scratch ----------------
__device__ bf16  g_XH[BTx*Dx],  g_XL[BTx*Dx];
__device__ bf16  g_WH[3*Dx*Dx], g_WL[3*Dx*Dx];     // [n][k]
__device__ bf16  g_WOH[Dx*Dx],  g_WOL[Dx*Dx];      // [n][k]
__device__ bf16  g_WFH[NFx*HDx], g_WFL[NFx*HDx];   // [f][d] split
__device__ float g_Q[BHx*Tx*HDx], g_K[BHx*Tx*HDx];
__device__ bf16  g_VH[BHx*Tx*HDx], g_VL[BHx*Tx*HDx];
__device__ bf16  g_QPH[BHx*Tx*NFx], g_QPL[BHx*Tx*NFx];
__device__ bf16  g_KPH[BHx*Tx*NFx], g_KPL[BHx*Tx*NFx];
__device__ float g_SC[SCANx*NFx*HDx], g_ZC[SCANx*NFx];
__device__ float g_SP[SCANx*NFx*HDx], g_ZP[SCANx*NFx];
__device__ bf16  g_YH[BTx*Dx], g_YL[BTx*Dx];

__device__ __forceinline__ void split_bf(float v, bf16 &h, bf16 &l) {
    h = __float2bfloat16(v);
    l = __float2bfloat16(v - __bfloat162float(h));
}
__device__ __forceinline__ float f2(bf16 v) { return __bfloat162float(v); }
__device__ __forceinline__ unsigned ldu(const bf16* p) {
    return *reinterpret_cast<const unsigned*>(p);
}
__device__ __forceinline__ void mma16816(float c[4], const unsigned a[4], const unsigned b[2]) {
    asm volatile(
        "mma.sync.aligned.m16n8k16.row.col.f32.bf16.bf16.f32 "
        "{%0,%1,%2,%3},{%4,%5,%6,%7},{%8,%9},{%0,%1,%2,%3};\n"
        : "+f"(c[0]), "+f"(c[1]), "+f"(c[2]), "+f"(c[3])
        : "r"(a[0]), "r"(a[1]), "r"(a[2]), "r"(a[3]), "r"(b[0]), "r"(b[1]));
}
__device__ __forceinline__ uint32_t s2u(const void* p) {
    uint32_t a;
    asm("{ .reg .u64 t; cvta.to.shared.u64 t, %1; cvt.u32.u64 %0, t; }" : "=r"(a) : "l"(p));
    return a;
}
__device__ __forceinline__ void cpa16s(uint32_t dst, const void* src) {
    asm volatile("cp.async.cg.shared.global [%0],[%1],16;\n" :: "r"(dst), "l"(src));
}
#define CPCOMMIT asm volatile("cp.async.commit_group;\n")
__device__ __forceinline__ void ldsm4(unsigned r[4], uint32_t a) {
    asm volatile("ldmatrix.sync.aligned.m8n8.x4.shared.b16 {%0,%1,%2,%3}, [%4];"
        : "=r"(r[0]), "=r"(r[1]), "=r"(r[2]), "=r"(r[3]) : "r"(a));
}

// ---------------- prep ----------------
__global__ void k_split_x(const float* __restrict__ x) {
    int i = blockIdx.x*256 + threadIdx.x;
    if (i < BTx*Dx) split_bf(x[i], g_XH[i], g_XL[i]);
}
// all weight prep in ONE launch: z<3 -> Wq/Wk/Wv, z==3 -> Wo, z==4 -> Wf
__global__ void k_prepw(const float* __restrict__ Wq, const float* __restrict__ Wk,
                        const float* __restrict__ Wv, const float* __restrict__ Wo,
                        const float* __restrict__ Wf) {
    if (blockIdx.z == 4) {
        if (blockIdx.y != 0) return;
        int i = blockIdx.x*256 + threadIdx.y*32 + threadIdx.x;
        if (i < NFx*HDx)
            split_bf(Wf[(i & 63)*NFx + (i >> 6)], g_WFH[i], g_WFL[i]);
        return;
    }
    __shared__ float tile[32][33];
    const float* W = blockIdx.z == 0 ? Wq : (blockIdx.z == 1 ? Wk : (blockIdx.z == 2 ? Wv : Wo));
    bf16* Dh = blockIdx.z == 3 ? g_WOH : g_WH + blockIdx.z*Dx*Dx;
    bf16* Dl = blockIdx.z == 3 ? g_WOL : g_WL + blockIdx.z*Dx*Dx;
    int x = blockIdx.x*32 + threadIdx.x;
    int y0 = blockIdx.y*32;
    #pragma unroll
    for (int j = 0; j < 32; j += 8)
        tile[threadIdx.y+j][threadIdx.x] = W[(y0+threadIdx.y+j)*1024 + x];
    __syncthreads();
    int n = blockIdx.x*32 + threadIdx.y;
    #pragma unroll
    for (int j = 0; j < 32; j += 8) {
        float v = tile[threadIdx.x][threadIdx.y+j];
        split_bf(v, Dh[(n+j)*1024 + y0 + threadIdx.x], Dl[(n+j)*1024 + y0 + threadIdx.x]);
    }
}

// ---------------- mma.sync split-3 GEMM, 128Mx128N tile, 2 CTAs/SM, 3-stage ----------------
#define SUBB 8192
#define STGB (4*SUBB)
#define GSMEM (3*STGB)
__global__ __launch_bounds__(256,2) void k_gemm(
        const bf16* __restrict__ Ah_, const bf16* __restrict__ Al_,
        const bf16* __restrict__ Bh_, const bf16* __restrict__ Bl_,
        int mode, float* __restrict__ out) {
    extern __shared__ char gsm[];
    uint32_t sb = s2u(gsm);
    int tid = threadIdx.x, lane = tid & 31, warp = tid >> 5;
    int g = lane >> 2, tg = lane & 3;
    int wm = warp >> 1, wn = warp & 1;            // 4x2 warps, each 32Mx64N
    int m0 = blockIdx.y*128, n0 = blockIdx.x*128;
    float acc[2][8][4] = {};

    auto load_stage = [&](int s, int kt) {
        uint32_t st = sb + s*STGB;
        #pragma unroll
        for (int i = 0; i < 8; i++) {
            int idx = tid + i*256;
            int arr = idx >> 9, c = idx & 511;
            int row = c >> 2, seg = c & 3;
            const bf16* gp = (arr == 0 ? Ah_ : arr == 1 ? Al_ : arr == 2 ? Bh_ : Bl_)
                           + (size_t)((arr < 2 ? m0 : n0) + row)*1024 + kt*32 + seg*8;
            uint32_t o = row*64 + ((seg ^ ((row>>1)&3))*16);
            cpa16s(st + arr*SUBB + o, gp);
        }
        CPCOMMIT;
    };
    load_stage(0, 0);
    load_stage(1, 1);
    for (int kt = 0; kt < 32; kt++) {
        if (kt == 31) asm volatile("cp.async.wait_group 0;\n");
        else          asm volatile("cp.async.wait_group 1;\n");
        __syncthreads();
        if (kt + 2 < 32) load_stage((kt+2)%3, kt+2);
        uint32_t st = sb + (kt%3)*STGB;
        #pragma unroll
        for (int kc = 0; kc < 2; kc++) {
            int sega = kc*2 + (lane >> 4);
            unsigned aH[2][4], aL[2][4], bH[4][4], bL[4][4];
            #pragma unroll
            for (int im = 0; im < 2; im++) {
                int r = wm*32 + im*16 + (lane & 15);
                uint32_t off = r*64 + ((sega ^ ((r>>1)&3))*16);
                ldsm4(aH[im], st + off);
                ldsm4(aL[im], st + SUBB + off);
            }
            #pragma unroll
            for (int p = 0; p < 4; p++) {
                int r = wn*64 + p*16 + (lane & 15);
                uint32_t off = r*64 + ((sega ^ ((r>>1)&3))*16);
                ldsm4(bH[p], st + 2*SUBB + off);
                ldsm4(bL[p], st + 3*SUBB + off);
            }
            #pragma unroll
            for (int im = 0; im < 2; im++)
                #pragma unroll
                for (int p = 0; p < 4; p++) {
                    unsigned b0h[2] = {bH[p][0], bH[p][2]}, b1h[2] = {bH[p][1], bH[p][3]};
                    unsigned b0l[2] = {bL[p][0], bL[p][2]}, b1l[2] = {bL[p][1], bL[p][3]};
                    mma16816(acc[im][2*p],   aH[im], b0h);
                    mma16816(acc[im][2*p],   aH[im], b0l);
                    mma16816(acc[im][2*p],   aL[im], b0h);
                    mma16816(acc[im][2*p+1], aH[im], b1h);
                    mma16816(acc[im][2*p+1], aH[im], b1l);
                    mma16816(acc[im][2*p+1], aL[im], b1h);
                }
        }
    }
    // ---- staged, coalesced epilogue ----
    __syncthreads();                               // all ldsm reads of pipeline smem done
    float* sOut = (float*)gsm;                     // 128*132 fp32 = 67.6KB <= 96KB
    #pragma unroll
    for (int im = 0; im < 2; im++)
        #pragma unroll
        for (int in = 0; in < 8; in++)
            #pragma unroll
            for (int e = 0; e < 4; e++) {
                int r = wm*32 + im*16 + g + ((e>>1)<<3);
                int c = wn*64 + in*8 + tg*2 + (e&1);
                sOut[r*132 + c] = acc[im][in][e];
            }
    __syncthreads();
    #pragma unroll 8
    for (int i = 0; i < 64; i++) {
        int idx = tid + i*256;
        int r = idx >> 7, c = idx & 127;
        float v = sOut[r*132 + c];
        int row = m0 + r, col = n0 + c;
        if (mode == 0) {
            int b = row >> 11, t = row & 2047;
            int which = col >> 10, cc = col & 1023;
            int off = ((b*Hx + (cc >> 6))*Tx + t)*HDx + (cc & 63);
            if (which == 0)      g_Q[off] = v;
            else if (which == 1) g_K[off] = v;
            else                 split_bf(v, g_VH[off], g_VL[off]);
        } else {
            out[(size_t)row*1024 + col] = v;
        }
    }
}

// ---------------- feature map via split-3 MMA, coalesced output ----------------
#define FP 72
#define FEAT_SMEM (4*128*FP*2 + 128*4 + 256*4)
__global__ __launch_bounds__(256,2) void k_feat() {
    extern __shared__ char fsm[];
    bf16* sqh = (bf16*)fsm;
    bf16* sql = sqh + 128*FP;
    bf16* swh = sql + 128*FP;
    bf16* swl = swh + 128*FP;
    float* sqn  = (float*)(swl + 128*FP);
    float* sqn2 = sqn + 128;
    int tid = threadIdx.x, lane = tid & 31, warp = tid >> 5;
    int g = lane >> 2, tg = lane & 3;
    const float* src = blockIdx.y ? g_K : g_Q;
    bf16* dh = blockIdx.y ? g_KPH : g_QPH;
    bf16* dl = blockIdx.y ? g_KPL : g_QPL;
    int tokbase = blockIdx.x * 128;

    // load + split in regs; exact fp32 row norms via warp butterfly
    #pragma unroll
    for (int i = 0; i < 32; i++) {
        int idx = tid + i*256;                   // d = tid&63 fixed, t = warp/2 + 4i
        int t = idx >> 6, d = idx & 63;
        float q = src[(tokbase + t)*HDx + d];
        split_bf(q, sqh[t*FP+d], sql[t*FP+d]);
        swh[t*FP+d] = g_WFH[idx];
        swl[t*FP+d] = g_WFL[idx];
        float part = q*q;
        #pragma unroll
        for (int off = 16; off; off >>= 1)
            part += __shfl_xor_sync(0xffffffffu, part, off);
        if (lane == 0) sqn2[t*2 + (warp & 1)] = part;
    }
    __syncthreads();
    if (tid < 128) sqn[tid] = 0.5f*(sqn2[2*tid] + sqn2[2*tid+1]);
    __syncthreads();

    int r0 = warp*16;
    float acc[16][4] = {};
    #pragma unroll
    for (int ks = 0; ks < 4; ks++) {
        int kc = ks*16;
        unsigned aH[4], aL[4];
        aH[0] = ldu(&sqh[(r0+g)*FP+kc+2*tg]);   aH[1] = ldu(&sqh[(r0+g+8)*FP+kc+2*tg]);
        aH[2] = ldu(&sqh[(r0+g)*FP+kc+2*tg+8]); aH[3] = ldu(&sqh[(r0+g+8)*FP+kc+2*tg+8]);
        aL[0] = ldu(&sql[(r0+g)*FP+kc+2*tg]);   aL[1] = ldu(&sql[(r0+g+8)*FP+kc+2*tg]);
        aL[2] = ldu(&sql[(r0+g)*FP+kc+2*tg+8]); aL[3] = ldu(&sql[(r0+g+8)*FP+kc+2*tg+8]);
        #pragma unroll
        for (int jn = 0; jn < 16; jn++) {
            int r = jn*8 + g;
            unsigned bH[2], bL[2];
            bH[0] = ldu(&swh[r*FP+kc+2*tg]); bH[1] = ldu(&swh[r*FP+kc+2*tg+8]);
            bL[0] = ldu(&swl[r*FP+kc+2*tg]); bL[1] = ldu(&swl[r*FP+kc+2*tg+8]);
            mma16816(acc[jn], aH, bH);
            mma16816(acc[jn], aH, bL);
            mma16816(acc[jn], aL, bH);
        }
    }
    // ---- staged, coalesced epilogue ----
    __syncthreads();                             // all MMA smem reads done
    bf16* soh = (bf16*)fsm;                      // 128*132 bf16
    bf16* sol = soh + 128*132;                   // total 67.6KB < 73.7KB (sqn regions safe)
    #pragma unroll
    for (int jn = 0; jn < 16; jn++)
        #pragma unroll
        for (int e = 0; e < 4; e++) {
            int row = r0 + g + ((e>>1)<<3);
            int f = jn*8 + 2*tg + (e&1);
            float p = __expf(acc[jn][e] - sqn[row]) * INV_SQRT_NF;
            split_bf(p, soh[row*132+f], sol[row*132+f]);
        }
    __syncthreads();
    #pragma unroll 8
    for (int i = 0; i < 32; i++) {
        int idx = tid + i*256;                   // 8192 u32 pairs
        int r = idx >> 6, cw = idx & 63;
        unsigned vh = *(unsigned*)&soh[r*132 + cw*2];
        unsigned vl = *(unsigned*)&sol[r*132 + cw*2];
        *(unsigned*)&dh[(tokbase+r)*NFx + cw*2] = vh;
        *(unsigned*)&dl[(tokbase+r)*NFx + cw*2] = vl;
    }
}

// ---------------- pass A: S_c = kp^T v (fp32, conflict-free), chunk=64 ----------------
#define PASSA_SMEM ((64*129 + 64*65)*4)
__global__ __launch_bounds__(256) void k_passA() {
    extern __shared__ float asm_[];
    float* skp = asm_;              // [t*129+f]
    float* svT = skp + 64*129;      // [d*65+t]
    int cta = blockIdx.x, tid = threadIdx.x;
    int base = (cta >> 5)*Tx + (cta & 31)*CHx;
    #pragma unroll
    for (int i = 0; i < 32; i++) {
        int idx = tid + i*256;
        int t = idx >> 7, f = idx & 127;
        skp[t*129+f] = f2(g_KPH[(base+t)*NFx+f]) + f2(g_KPL[(base+t)*NFx+f]);
    }
    #pragma unroll
    for (int i = 0; i < 16; i++) {
        int idx = tid + i*256;
        int s = idx >> 6, d = idx & 63;
        svT[d*65+s] = f2(g_VH[(base+s)*HDx+d]) + f2(g_VL[(base+s)*HDx+d]);
    }
    __syncthreads();
    if (tid < 128) {
        float s = 0.f;
        #pragma unroll 16
        for (int t = 0; t < 64; t++) s += skp[t*129 + tid];
        g_ZC[cta*NFx + tid] = s;
    }
    int f0 = (tid >> 3)*4, d0 = (tid & 7)*8;
    float acc[4][8] = {};
    #pragma unroll 4
    for (int t = 0; t < 64; t++) {
        float kv[4], vv[8];
        #pragma unroll
        for (int i = 0; i < 4; i++) kv[i] = skp[t*129 + f0 + i];
        #pragma unroll
        for (int j = 0; j < 8; j++) vv[j] = svT[(d0+j)*65 + t];
        #pragma unroll
        for (int i = 0; i < 4; i++)
            #pragma unroll
            for (int j = 0; j < 8; j++) acc[i][j] += kv[i]*vv[j];
    }
    #pragma unroll
    for (int i = 0; i < 4; i++)
        #pragma unroll
        for (int j = 0; j < 8; j++)
            g_SC[cta*(NFx*HDx) + (f0+i)*HDx + d0 + j] = acc[i][j];
}

// ---------------- exclusive prefix over chunks, software-prefetched ----------------
__global__ __launch_bounds__(256) void k_prefix() {
    int bh = blockIdx.x, fg = blockIdx.y, tid = threadIdx.x;
    int cb = bh*NCx;
    int b0 = cb*(NFx*HDx) + fg*512;
    float s0 = 0.f, s1 = 0.f, z = 0.f;
    float a0 = g_SC[b0 + tid], a1 = g_SC[b0 + 256 + tid];
    float zc = (tid < 8) ? g_ZC[cb*NFx + fg*8 + tid] : 0.f;
    #pragma unroll 4
    for (int c = 0; c < NCx; c++) {
        float n0 = 0.f, n1 = 0.f, nz = 0.f;
        if (c + 1 < NCx) {
            int bn = b0 + NFx*HDx;
            n0 = g_SC[bn + tid]; n1 = g_SC[bn + 256 + tid];
            if (tid < 8) nz = g_ZC[(cb+c+1)*NFx + fg*8 + tid];
        }
        g_SP[b0 + tid] = s0;        s0 += a0;
        g_SP[b0 + 256 + tid] = s1;  s1 += a1;
        if (tid < 8) { g_ZP[(cb+c)*NFx + fg*8 + tid] = z; z += zc; }
        a0 = n0; a1 = n1; zc = nz; b0 += NFx*HDx;
    }
}

// ---------------- pass C: MMA intra + inter, chunk=64, 2 CTAs/SM ----------------
#define CP1 132
#define CP2 72
#define PASSC_SMEM ((4*64*CP1 + 4*64*CP2)*2 + (NFx+64)*4)
__global__ __launch_bounds__(256,2) void k_passC() {
    extern __shared__ char csm[];
    bf16* sqh = (bf16*)csm;            bf16* sql = sqh + 64*CP1;
    bf16* skh = sql + 64*CP1;          bf16* skl = skh + 64*CP1;
    bf16* sAh = skl + 64*CP1;          bf16* sAl = sAh + 64*CP2;
    bf16* svh = sAl + 64*CP2;          bf16* svl = svh + 64*CP2;
    bf16* sph = skh;                   bf16* spl = skl;   // alias: kp dead after phase1
    float* szp  = (float*)(svl + 64*CP2);
    float* sden = szp + NFx;

    int cta = blockIdx.x, tid = threadIdx.x;
    int bh = cta >> 5, c = cta & 31;
    int base = bh*Tx + c*CHx;
    int lane = tid & 31, warp = tid >> 5, g = lane >> 2, tg = lane & 3;

    #pragma unroll
    for (int i = 0; i < 32; i++) {
        int idx = tid + i*256;
        int t = idx >> 7, f = idx & 127;
        sqh[t*CP1+f] = g_QPH[(base+t)*NFx+f];  sql[t*CP1+f] = g_QPL[(base+t)*NFx+f];
        skh[t*CP1+f] = g_KPH[(base+t)*NFx+f];  skl[t*CP1+f] = g_KPL[(base+t)*NFx+f];
    }
    if (tid < NFx) szp[tid] = g_ZP[cta*NFx + tid];
    __syncthreads();

    // phase 1: A[t][s] = qp.kp^T (M64 N64 K128)
    {
        int wm = warp & 1, wn = warp >> 1;
        float acc[2][2][4] = {};
        #pragma unroll
        for (int ks = 0; ks < 8; ks++) {
            int kc = ks*16;
            unsigned aH[2][4], aL[2][4], bH[2][2], bL[2][2];
            #pragma unroll
            for (int im = 0; im < 2; im++) {
                int r = wm*32 + im*16;
                aH[im][0] = ldu(&sqh[(r+g)*CP1+kc+2*tg]);   aH[im][1] = ldu(&sqh[(r+g+8)*CP1+kc+2*tg]);
                aH[im][2] = ldu(&sqh[(r+g)*CP1+kc+2*tg+8]); aH[im][3] = ldu(&sqh[(r+g+8)*CP1+kc+2*tg+8]);
                aL[im][0] = ldu(&sql[(r+g)*CP1+kc+2*tg]);   aL[im][1] = ldu(&sql[(r+g+8)*CP1+kc+2*tg]);
                aL[im][2] = ldu(&sql[(r+g)*CP1+kc+2*tg+8]); aL[im][3] = ldu(&sql[(r+g+8)*CP1+kc+2*tg+8]);
            }
            #pragma unroll
            for (int in = 0; in < 2; in++) {
                int r = wn*16 + in*8 + g;
                bH[in][0] = ldu(&skh[r*CP1+kc+2*tg]); bH[in][1] = ldu(&skh[r*CP1+kc+2*tg+8]);
                bL[in][0] = ldu(&skl[r*CP1+kc+2*tg]); bL[in][1] = ldu(&skl[r*CP1+kc+2*tg+8]);
            }
            #pragma unroll
            for (int im = 0; im < 2; im++)
                #pragma unroll
                for (int in = 0; in < 2; in++) {
                    mma16816(acc[im][in], aH[im], bH[in]);
                    mma16816(acc[im][in], aH[im], bL[in]);
                    mma16816(acc[im][in], aL[im], bH[in]);
                }
        }
        #pragma unroll
        for (int im = 0; im < 2; im++)
            #pragma unroll
            for (int in = 0; in < 2; in++)
                #pragma unroll
                for (int e = 0; e < 4; e++) {
                    int t = wm*32 + im*16 + g + ((e>>1)<<3);
                    int s = wn*16 + in*8 + 2*tg + (e&1);
                    float v = (s <= t) ? acc[im][in][e] : 0.f;
                    split_bf(v, sAh[t*CP2+s], sAl[t*CP2+s]);
                }
    }
    __syncthreads();   // all kp reads + A writes done before sk region reused for SP

    // load vT; SP into the freed kp region; den = rowsum(A) + qp.zp + eps
    #pragma unroll
    for (int i = 0; i < 16; i++) {
        int idx = tid + i*256;
        int s = idx >> 6, d = idx & 63;
        svh[d*CP2+s] = g_VH[(base+s)*HDx+d];  svl[d*CP2+s] = g_VL[(base+s)*HDx+d];
    }
    #pragma unroll
    for (int i = 0; i < 32; i++) {
        int idx = tid + i*256;
        int f = idx >> 6, d = idx & 63;
        float sp = g_SP[cta*(NFx*HDx) + f*HDx + d];
        split_bf(sp, sph[d*CP1+f], spl[d*CP1+f]);
    }
    if (tid < 64) {
        float rs = 0.f, qz = 0.f;
        #pragma unroll 8
        for (int s = 0; s < 64; s++) rs += f2(sAh[tid*CP2+s]) + f2(sAl[tid*CP2+s]);
        #pragma unroll 8
        for (int f = 0; f < NFx; f++) qz += (f2(sqh[tid*CP1+f]) + f2(sql[tid*CP1+f]))*szp[f];
        sden[tid] = rs + qz + 1e-6f;
    }
    __syncthreads();   // sv, sp, den visible

    // phase 2: y[t][d] = A.v + qp.SP (M64 N64, K=64 then K=128)
    int r0 = (warp & 3)*16, d0 = (warp >> 2)*32;
    float acc[4][4] = {};
    #pragma unroll
    for (int ks = 0; ks < 4; ks++) {
        int kc = ks*16;
        unsigned aH[4], aL[4];
        aH[0] = ldu(&sAh[(r0+g)*CP2+kc+2*tg]);   aH[1] = ldu(&sAh[(r0+g+8)*CP2+kc+2*tg]);
        aH[2] = ldu(&sAh[(r0+g)*CP2+kc+2*tg+8]); aH[3] = ldu(&sAh[(r0+g+8)*CP2+kc+2*tg+8]);
        aL[0] = ldu(&sAl[(r0+g)*CP2+kc+2*tg]);   aL[1] = ldu(&sAl[(r0+g+8)*CP2+kc+2*tg]);
        aL[2] = ldu(&sAl[(r0+g)*CP2+kc+2*tg+8]); aL[3] = ldu(&sAl[(r0+g+8)*CP2+kc+2*tg+8]);
        #pragma unroll
        for (int in = 0; in < 4; in++) {
            int r = d0 + in*8 + g;
            unsigned bH[2], bL[2];
            bH[0] = ldu(&svh[r*CP2+kc+2*tg]); bH[1] = ldu(&svh[r*CP2+kc+2*tg+8]);
            bL[0] = ldu(&svl[r*CP2+kc+2*tg]); bL[1] = ldu(&svl[r*CP2+kc+2*tg+8]);
            mma16816(acc[in], aH, bH);
            mma16816(acc[in], aH, bL);
            mma16816(acc[in], aL, bH);
        }
    }
    #pragma unroll
    for (int ks = 0; ks < 8; ks++) {
        int kc = ks*16;
        unsigned aH[4], aL[4];
        aH[0] = ldu(&sqh[(r0+g)*CP1+kc+2*tg]);   aH[1] = ldu(&sqh[(r0+g+8)*CP1+kc+2*tg]);
        aH[2] = ldu(&sqh[(r0+g)*CP1+kc+2*tg+8]); aH[3] = ldu(&sqh[(r0+g+8)*CP1+kc+2*tg+8]);
        aL[0] = ldu(&sql[(r0+g)*CP1+kc+2*tg]);   aL[1] = ldu(&sql[(r0+g+8)*CP1+kc+2*tg]);
        aL[2] = ldu(&sql[(r0+g)*CP1+kc+2*tg+8]); aL[3] = ldu(&sql[(r0+g+8)*CP1+kc+2*tg+8]);
        #pragma unroll
        for (int in = 0; in < 4; in++) {
            int r = d0 + in*8 + g;
            unsigned bH[2], bL[2];
            bH[0] = ldu(&sph[r*CP1+kc+2*tg]); bH[1] = ldu(&sph[r*CP1+kc+2*tg+8]);
            bL[0] = ldu(&spl[r*CP1+kc+2*tg]); bL[1] = ldu(&spl[r*CP1+kc+2*tg+8]);
            mma16816(acc[in], aH, bH);
            mma16816(acc[in], aH, bL);
            mma16816(acc[in], aL, bH);
        }
    }
    __syncthreads();
    int b = bh >> 4, h = bh & 15;
    #pragma unroll
    for (int in = 0; in < 4; in++)
        #pragma unroll
        for (int e = 0; e < 4; e++) {
            int t = r0 + g + ((e>>1)<<3);
            int d = d0 + in*8 + 2*tg + (e&1);
            float v = acc[in][e] / sden[t];
            int m = b*Tx + c*CHx + t;
            split_bf(v, g_YH[m*1024 + h*HDx + d], g_YL[m*1024 + h*HDx + d]);
        }
}

// ---------------- launch ----------------
extern "C" void kernel_launch(void* const* d_in, const int* in_sizes, int n_in,
                              void* d_out, int out_size) {
    const float* x  = (const float*)d_in[0];
    const float* Wq = (const float*)d_in[1];
    const float* Wk = (const float*)d_in[2];
    const float* Wv = (const float*)d_in[3];
    const float* Wo = (const float*)d_in[4];
    const float* Wf = (const float*)d_in[5];
    float* out = (float*)d_out;

    cudaFuncSetAttribute(k_gemm,  cudaFuncAttributeMaxDynamicSharedMemorySize, GSMEM);
    cudaFuncSetAttribute(k_feat,  cudaFuncAttributeMaxDynamicSharedMemorySize, FEAT_SMEM);
    cudaFuncSetAttribute(k_passA, cudaFuncAttributeMaxDynamicSharedMemorySize, PASSA_SMEM);
    cudaFuncSetAttribute(k_passC, cudaFuncAttributeMaxDynamicSharedMemorySize, PASSC_SMEM);

    bf16 *XH, *XL, *WH, *WL, *WOH, *WOL, *YH, *YL;
    cudaGetSymbolAddress((void**)&XH, g_XH);   cudaGetSymbolAddress((void**)&XL, g_XL);
    cudaGetSymbolAddress((void**)&WH, g_WH);   cudaGetSymbolAddress((void**)&WL, g_WL);
    cudaGetSymbolAddress((void**)&WOH, g_WOH); cudaGetSymbolAddress((void**)&WOL, g_WOL);
    cudaGetSymbolAddress((void**)&YH, g_YH);   cudaGetSymbolAddress((void**)&YL, g_YL);

    k_split_x<<<BTx*Dx/256, 256>>>(x);                                   // 1
    k_prepw<<<dim3(32,32,5), dim3(32,8)>>>(Wq, Wk, Wv, Wo, Wf);          // 2
    k_gemm<<<dim3(24, 64), 256, GSMEM>>>(XH, XL, WH, WL, 0, nullptr);    // 3
    k_feat<<<dim3(BHx*Tx/128, 2), 256, FEAT_SMEM>>>();                   // 4 <- profile target
    k_passA<<<SCANx, 256, PASSA_SMEM>>>();                               // 5
    k_prefix<<<dim3(BHx, 16), 256>>>();                                  // 6
    k_passC<<<SCANx, 256, PASSC_SMEM>>>();                               // 7
    k_gemm<<<dim3(8, 64), 256, GSMEM>>>(YH, YL, WOH, WOL, 1, out);       // 8
}